// round 5
// baseline (speedup 1.0000x reference)
#include <cuda_runtime.h>
#include <math.h>

#define T_LEN 512
#define B_SZ  64
#define D_SZ  1024
#define H_SZ  512
#define L_SZ  5

#define NCTA 128
#define NTHR 256
#define NBAR 16384u

// dynamic smem: 10*128*8 float4 weights (160KB) + 2*32*64 float hs (16KB)
#define WDUP_F4   (10 * 128 * 8)
#define SMEM_HS   (WDUP_F4 * 16)
#define SMEM_TOT  (SMEM_HS + 2 * 32 * 64 * 4)

typedef unsigned long long ull;

// ---------------- device-global scratch ----------------------------------------
__device__ float    g_XHt[T_LEN * H_SZ * B_SZ];   // [t][j][b]
__device__ float    g_XCt[T_LEN * H_SZ * B_SZ];   // [t][j][b]
__device__ float    g_h[2][H_SZ * B_SZ];          // hidden double buffer [j][b]
__device__ float    g_part[2][4][H_SZ][B_SZ];     // [gate][kg][j][b]
__device__ unsigned g_flags[NCTA];
__device__ unsigned g_cur  = 0;
__device__ unsigned g_next = 0;

__global__ void bump_kernel() {
    unsigned b = g_next;
    g_cur  = b;
    g_next = b + NBAR;
}

__device__ __forceinline__ ull fma2(ull a, ull b, ull c) {
    ull d;
    asm("fma.rn.f32x2 %0, %1, %2, %3;" : "=l"(d) : "l"(a), "l"(b), "l"(c));
    return d;
}

// grid barrier: per-CTA flags, st.release / ld.acquire, monotonic generations
__device__ __forceinline__ void gbar(int tid, int cta, unsigned gen) {
    __syncthreads();
    if (tid == 0) {
        asm volatile("st.release.gpu.global.u32 [%0], %1;"
                     :: "l"(&g_flags[cta]), "r"(gen) : "memory");
    }
    if (tid < NCTA) {
        unsigned v;
        do {
            asm volatile("ld.acquire.gpu.global.u32 %0, [%1];"
                         : "=r"(v) : "l"(&g_flags[tid]) : "memory");
        } while ((int)(v - gen) < 0);
    }
    __syncthreads();
}

// ---------------- precompute: XHt/XCt[t][j][b] = x[t,b,:]@W[:,j] + bias[j] ------
__global__ void __launch_bounds__(NTHR) proj_kernel(
    const float* __restrict__ x,
    const float* __restrict__ Ww,
    const float* __restrict__ Wb,
    const int gate)
{
    __shared__ float As[32][128];
    __shared__ float Bs[32][64];
    float* __restrict__ dst = gate ? g_XCt : g_XHt;

    const int tid = threadIdx.x;
    const int bm  = blockIdx.x * 128;
    const int bn  = blockIdx.y * 64;
    const int tm  = tid & 15;
    const int tn  = tid >> 4;

    float acc[8][4];
#pragma unroll
    for (int i = 0; i < 8; i++)
#pragma unroll
        for (int j = 0; j < 4; j++) acc[i][j] = 0.0f;

    for (int k0 = 0; k0 < D_SZ; k0 += 32) {
#pragma unroll
        for (int r = 0; r < 4; r++) {
            int lin = tid + r * 256;
            int m = lin >> 3, kq = lin & 7;
            float4 v = *(const float4*)(x + (size_t)(bm + m) * D_SZ + k0 + kq * 4);
            As[kq * 4 + 0][m] = v.x;
            As[kq * 4 + 1][m] = v.y;
            As[kq * 4 + 2][m] = v.z;
            As[kq * 4 + 3][m] = v.w;
        }
#pragma unroll
        for (int r = 0; r < 2; r++) {
            int lin = tid + r * 256;
            int kk = lin >> 4, jq = lin & 15;
            *(float4*)&Bs[kk][jq * 4] =
                *(const float4*)(Ww + (size_t)(k0 + kk) * H_SZ + bn + jq * 4);
        }
        __syncthreads();
#pragma unroll
        for (int k = 0; k < 32; k++) {
            float4 a0 = *(const float4*)&As[k][tm * 4];
            float4 a1 = *(const float4*)&As[k][64 + tm * 4];
            float4 bv = *(const float4*)&Bs[k][tn * 4];
            float av[8] = {a0.x, a0.y, a0.z, a0.w, a1.x, a1.y, a1.z, a1.w};
            float bw[4] = {bv.x, bv.y, bv.z, bv.w};
#pragma unroll
            for (int i = 0; i < 8; i++)
#pragma unroll
                for (int j = 0; j < 4; j++)
                    acc[i][j] = fmaf(av[i], bw[j], acc[i][j]);
        }
        __syncthreads();
    }

#pragma unroll
    for (int i = 0; i < 8; i++) {
        int m = bm + ((i < 4) ? (tm * 4 + i) : (64 + tm * 4 + i - 4));
        int t = m >> 6, b = m & 63;
#pragma unroll
        for (int j = 0; j < 4; j++) {
            int jj = bn + tn * 4 + j;
            dst[(size_t)t * (H_SZ * B_SZ) + (size_t)jj * B_SZ + b] = acc[i][j] + Wb[jj];
        }
    }
}

// ---------------- persistent sequential kernel ---------------------------------
// 128 CTAs = 32 j-groups (16 j) x 4 k-groups (128 k). ALL recurrent weights for
// this CTA's (j,k) slice live in SMEM, pre-duplicated {w,w} for fma.f32x2,
// loaded ONCE. Per layer: stream hidden (32 KB) through a double-buffered smem
// chunk, 4 FFMA2/k/thread, write g_part, barrier, phase-B combine, barrier.
__global__ void __launch_bounds__(NTHR, 1) rhn_seq_kernel(
    const float* __restrict__ RHw, const float* __restrict__ RHb,
    const float* __restrict__ RCw, const float* __restrict__ RCb,
    float* __restrict__ out)
{
    extern __shared__ __align__(16) char smem_raw[];
    float4* __restrict__ wdup = (float4*)smem_raw;        // [(l*2+g)*128 + k][8]
    float*  __restrict__ hs   = (float*)(smem_raw + SMEM_HS); // [2][32][64]

    const int tid = threadIdx.x;
    const int cta = blockIdx.x;
    const unsigned base = __ldcg(&g_cur);
    unsigned bar = 0;

    const int jg = cta & 31;
    const int kg = cta >> 5;
    const int j0 = jg * 16;
    const int k0 = kg * 128;

    // ---- one-time weight preload into smem (duplicated for fma2) ----
#pragma unroll
    for (int lg = 0; lg < 10; lg++) {
        const float* __restrict__ src =
            ((lg & 1) ? RCw : RHw) + (size_t)(lg >> 1) * (H_SZ * H_SZ);
#pragma unroll
        for (int i = tid; i < 512; i += NTHR) {
            int k = i >> 2, j4 = i & 3;
            float4 w = *(const float4*)(src + (size_t)(k0 + k) * H_SZ + j0 + j4 * 4);
            wdup[(lg * 128 + k) * 8 + j4 * 2]     = make_float4(w.x, w.x, w.y, w.y);
            wdup[(lg * 128 + k) * 8 + j4 * 2 + 1] = make_float4(w.z, w.z, w.w, w.w);
        }
    }

    // h0 = 0
    __stcg(&g_h[0][cta * NTHR + tid], 0.0f);
    gbar(tid, cta, base + (++bar));

    // phase-A mapping: jp(2j) x gate x byq(4b)
    const int jp   = tid & 7;
    const int gate = (tid >> 3) & 1;
    const int byq  = tid >> 4;

    // phase-B mapping: one element per thread
    const int e  = cta * NTHR + tid;
    const int eb = e & 63;
    const int ej = e >> 6;

    int p = 0;
    for (int pass = 0; pass < 2; pass++)
    for (int t = 0; t < T_LEN; t++)
    for (int l = 0; l < L_SZ; l++) {
        const float* __restrict__ hp = g_h[p];
        const float4* __restrict__ wl = wdup + (size_t)((l * 2 + gate) * 128) * 8;

        ull a0 = 0ull, a1 = 0ull, a2 = 0ull, a3 = 0ull;

        // prefetch chunk 0 of hidden (32k x 64b)
        float4 ph0, ph1;
        {
            const float4* h4 = (const float4*)(hp + k0 * B_SZ);
            ph0 = __ldcg(h4 + tid);
            ph1 = __ldcg(h4 + tid + 256);
        }
#pragma unroll
        for (int c = 0; c < 4; c++) {
            float* buf = hs + (c & 1) * 2048;
            ((float4*)buf)[tid]       = ph0;
            ((float4*)buf)[tid + 256] = ph1;
            __syncthreads();
            if (c < 3) {
                const float4* h4 = (const float4*)(hp + (k0 + (c + 1) * 32) * B_SZ);
                ph0 = __ldcg(h4 + tid);
                ph1 = __ldcg(h4 + tid + 256);
            }
            const float4* wc = wl + (c * 32) * 8 + jp;
#pragma unroll
            for (int kk = 0; kk < 32; kk++) {
                const ulonglong2 hv = *(const ulonglong2*)&buf[kk * 64 + byq * 4];
                const ulonglong2 rv = *(const ulonglong2*)&wc[kk * 8];
                a0 = fma2(hv.x, rv.x, a0);   // {b0,b1} j_even
                a1 = fma2(hv.y, rv.x, a1);   // {b2,b3} j_even
                a2 = fma2(hv.x, rv.y, a2);   // {b0,b1} j_odd
                a3 = fma2(hv.y, rv.y, a3);   // {b2,b3} j_odd
            }
        }
        {
            float2 f0 = *(float2*)&a0, f1 = *(float2*)&a1;
            float2 f2 = *(float2*)&a2, f3 = *(float2*)&a3;
            int j = j0 + jp * 2;
            *(float4*)&g_part[gate][kg][j][byq * 4] =
                make_float4(f0.x, f0.y, f1.x, f1.y);
            *(float4*)&g_part[gate][kg][j + 1][byq * 4] =
                make_float4(f2.x, f2.y, f3.x, f3.y);
        }
        gbar(tid, cta, base + (++bar));

        // ---- phase B ----
        {
            float sH = __ldcg(&g_part[0][0][ej][eb]) + __ldcg(&g_part[0][1][ej][eb])
                     + __ldcg(&g_part[0][2][ej][eb]) + __ldcg(&g_part[0][3][ej][eb]);
            float sC = __ldcg(&g_part[1][0][ej][eb]) + __ldcg(&g_part[1][1][ej][eb])
                     + __ldcg(&g_part[1][2][ej][eb]) + __ldcg(&g_part[1][3][ej][eb]);
            sH += RHb[l * H_SZ + ej];
            sC += RCb[l * H_SZ + ej];
            if (l == 0) {
                sH += __ldcg(&g_XHt[(size_t)t * (H_SZ * B_SZ) + e]);
                sC += __ldcg(&g_XCt[(size_t)t * (H_SZ * B_SZ) + e]);
            }
            float hold = __ldcg(&g_h[p][e]);
            float hl = tanhf(sH);
            float tl = 1.0f / (1.0f + __expf(-sC));
            float hn = fmaf(tl, hl - hold, hold);
            __stcg(&g_h[p ^ 1][e], hn);
            if (l == L_SZ - 1) {
                size_t o = (size_t)t * (B_SZ * 2 * H_SZ) + (size_t)eb * (2 * H_SZ)
                         + (size_t)pass * H_SZ + ej;
                out[o] = hn;
                if (t == T_LEN - 1) {
                    out[(size_t)T_LEN * (B_SZ * 2 * H_SZ) + (size_t)eb * (2 * H_SZ)
                        + (size_t)pass * H_SZ + ej] = hn;
                }
            }
        }
        gbar(tid, cta, base + (++bar));
        p ^= 1;
    }
}

extern "C" void kernel_launch(void* const* d_in, const int* in_sizes, int n_in,
                              void* d_out, int out_size)
{
    const float* x   = (const float*)d_in[0];
    const float* WHw = (const float*)d_in[1];
    const float* WHb = (const float*)d_in[2];
    const float* WCw = (const float*)d_in[3];
    const float* WCb = (const float*)d_in[4];
    const float* RHw = (const float*)d_in[5];
    const float* RHb = (const float*)d_in[6];
    const float* RCw = (const float*)d_in[7];
    const float* RCb = (const float*)d_in[8];
    float* out = (float*)d_out;

    static int smem_set = 0;
    if (!smem_set) {
        cudaFuncSetAttribute(rhn_seq_kernel,
                             cudaFuncAttributeMaxDynamicSharedMemorySize, SMEM_TOT);
        smem_set = 1;
    }

    bump_kernel<<<1, 1>>>();
    dim3 pg(256, 8);
    proj_kernel<<<pg, NTHR>>>(x, WHw, WHb, 0);
    proj_kernel<<<pg, NTHR>>>(x, WCw, WCb, 1);
    rhn_seq_kernel<<<NCTA, NTHR, SMEM_TOT>>>(RHw, RHb, RCw, RCb, out);
}

// round 6
// speedup vs baseline: 1.0028x; 1.0028x over previous
#include <cuda_runtime.h>
#include <math.h>

#define T_LEN 512
#define B_SZ  64
#define D_SZ  1024
#define H_SZ  512
#define L_SZ  5

#define NCTA 128
#define NTHR 256
#define NBAR 16384u

// ---------------- device-global scratch ----------------------------------------
__device__ float    g_XHt[T_LEN * H_SZ * B_SZ];   // [t][j][b]
__device__ float    g_XCt[T_LEN * H_SZ * B_SZ];   // [t][j][b]
__device__ float    g_h[2][H_SZ * B_SZ];          // hidden double buffer [j][b]
__device__ float    g_part[2][4][H_SZ][B_SZ];     // [gate][kg][j][b]
__device__ unsigned g_flags[NCTA];
__device__ unsigned g_cur  = 0;
__device__ unsigned g_next = 0;

__global__ void bump_kernel() {
    unsigned b = g_next;
    g_cur  = b;
    g_next = b + NBAR;
}

// grid barrier: per-CTA flags, release/acquire, monotonic generations.
// Release chain: CTA writes -> __syncthreads (cta scope) -> thread0 st.release.gpu
// -> remote ld.acquire.gpu (transitive happens-before per PTX memory model).
__device__ __forceinline__ void gbar(int tid, int cta, unsigned gen) {
    __syncthreads();
    if (tid == 0) {
        asm volatile("st.release.gpu.global.u32 [%0], %1;"
                     :: "l"(&g_flags[cta]), "r"(gen) : "memory");
    }
    if (tid < NCTA) {
        unsigned v;
        do {
            asm volatile("ld.acquire.gpu.global.u32 %0, [%1];"
                         : "=r"(v) : "l"(&g_flags[tid]) : "memory");
        } while ((int)(v - gen) < 0);
    }
    __syncthreads();
}

// ---------------- precompute: XHt/XCt[t][j][b] = x[t,b,:]@W[:,j] + bias[j] ------
__global__ void __launch_bounds__(NTHR) proj_kernel(
    const float* __restrict__ x,
    const float* __restrict__ Ww,
    const float* __restrict__ Wb,
    const int gate)
{
    __shared__ float As[32][128];
    __shared__ float Bs[32][64];
    float* __restrict__ dst = gate ? g_XCt : g_XHt;

    const int tid = threadIdx.x;
    const int bm  = blockIdx.x * 128;
    const int bn  = blockIdx.y * 64;
    const int tm  = tid & 15;
    const int tn  = tid >> 4;

    float acc[8][4];
#pragma unroll
    for (int i = 0; i < 8; i++)
#pragma unroll
        for (int j = 0; j < 4; j++) acc[i][j] = 0.0f;

    for (int k0 = 0; k0 < D_SZ; k0 += 32) {
#pragma unroll
        for (int r = 0; r < 4; r++) {
            int lin = tid + r * 256;
            int m = lin >> 3, kq = lin & 7;
            float4 v = *(const float4*)(x + (size_t)(bm + m) * D_SZ + k0 + kq * 4);
            As[kq * 4 + 0][m] = v.x;
            As[kq * 4 + 1][m] = v.y;
            As[kq * 4 + 2][m] = v.z;
            As[kq * 4 + 3][m] = v.w;
        }
#pragma unroll
        for (int r = 0; r < 2; r++) {
            int lin = tid + r * 256;
            int kk = lin >> 4, jq = lin & 15;
            *(float4*)&Bs[kk][jq * 4] =
                *(const float4*)(Ww + (size_t)(k0 + kk) * H_SZ + bn + jq * 4);
        }
        __syncthreads();
#pragma unroll
        for (int k = 0; k < 32; k++) {
            float4 a0 = *(const float4*)&As[k][tm * 4];
            float4 a1 = *(const float4*)&As[k][64 + tm * 4];
            float4 bv = *(const float4*)&Bs[k][tn * 4];
            float av[8] = {a0.x, a0.y, a0.z, a0.w, a1.x, a1.y, a1.z, a1.w};
            float bw[4] = {bv.x, bv.y, bv.z, bv.w};
#pragma unroll
            for (int i = 0; i < 8; i++)
#pragma unroll
                for (int j = 0; j < 4; j++)
                    acc[i][j] = fmaf(av[i], bw[j], acc[i][j]);
        }
        __syncthreads();
    }

#pragma unroll
    for (int i = 0; i < 8; i++) {
        int m = bm + ((i < 4) ? (tm * 4 + i) : (64 + tm * 4 + i - 4));
        int t = m >> 6, b = m & 63;
#pragma unroll
        for (int j = 0; j < 4; j++) {
            int jj = bn + tn * 4 + j;
            dst[(size_t)t * (H_SZ * B_SZ) + (size_t)jj * B_SZ + b] = acc[i][j] + Wb[jj];
        }
    }
}

// ---------------- persistent sequential kernel (R2 structure + flag barrier) ----
// Phase A: 128 CTAs = 32 j-groups x 4 k-groups; CTA tile = 64b x 16j x 128k x 2g.
//   Thread = 4b x 1j x 2 gates: per-k = 2 scalar LDS + 1 LDS.128 + 8 FFMA
//   (FMA-pipe bound at 32 cyc/k/SMSP).
// Phase B: 1 element/thread: reduce 4 partials + bias (+X at l==0),
//   tanh / __expf sigmoid, highway combine.
__global__ void __launch_bounds__(NTHR, 1) rhn_seq_kernel(
    const float* __restrict__ RHw, const float* __restrict__ RHb,
    const float* __restrict__ RCw, const float* __restrict__ RCb,
    float* __restrict__ out)
{
    const int tid = threadIdx.x;
    const int cta = blockIdx.x;
    const unsigned base = __ldcg(&g_cur);
    unsigned bar = 0;

    __shared__ __align__(16) float hs[32][64];      // [k][b]
    __shared__ __align__(16) float rhs_s[32][16];   // [k][j]
    __shared__ __align__(16) float rcs_s[32][16];   // [k][j]

    __stcg(&g_h[0][cta * NTHR + tid], 0.0f);
    gbar(tid, cta, base + (++bar));

    const int jx  = tid & 15;         // j within 16-wide group
    const int byq = tid >> 4;         // b quad (4 consecutive b)
    const int jg  = cta & 31;
    const int kg  = cta >> 5;
    const int j0  = jg * 16;
    const int k0  = kg * 128;

    const int kk_r = tid >> 3, jq_r = tid & 7;

    const int e  = cta * NTHR + tid;  // phase-B element
    const int eb = e & 63;
    const int ej = e >> 6;

    int p = 0;
    for (int pass = 0; pass < 2; pass++)
    for (int t = 0; t < T_LEN; t++)
    for (int l = 0; l < L_SZ; l++) {
        const float* __restrict__ Rh = RHw + (size_t)l * H_SZ * H_SZ;
        const float* __restrict__ Rc = RCw + (size_t)l * H_SZ * H_SZ;
        const float* __restrict__ hp = g_h[p];

        float aH0 = 0, aH1 = 0, aH2 = 0, aH3 = 0;
        float aC0 = 0, aC1 = 0, aC2 = 0, aC3 = 0;

        // prefetch chunk 0
        float4 h0v, h1v;
        float2 r0v, r1v;
        {
            const float4* h4 = (const float4*)(hp + k0 * 64);
            h0v = __ldcg(h4 + tid);
            h1v = __ldcg(h4 + tid + 256);
            r0v = *(const float2*)(Rh + (size_t)(k0 + kk_r) * H_SZ + j0 + 2 * jq_r);
            r1v = *(const float2*)(Rc + (size_t)(k0 + kk_r) * H_SZ + j0 + 2 * jq_r);
        }
#pragma unroll
        for (int c = 0; c < 4; c++) {
            __syncthreads();
            ((float4*)hs)[tid]       = h0v;
            ((float4*)hs)[tid + 256] = h1v;
            ((float2*)rhs_s)[tid]    = r0v;
            ((float2*)rcs_s)[tid]    = r1v;
            __syncthreads();
            if (c < 3) {
                int kb = k0 + (c + 1) * 32;
                const float4* h4 = (const float4*)(hp + kb * 64);
                h0v = __ldcg(h4 + tid);
                h1v = __ldcg(h4 + tid + 256);
                r0v = *(const float2*)(Rh + (size_t)(kb + kk_r) * H_SZ + j0 + 2 * jq_r);
                r1v = *(const float2*)(Rc + (size_t)(kb + kk_r) * H_SZ + j0 + 2 * jq_r);
            }
#pragma unroll
            for (int kk = 0; kk < 32; kk++) {
                float rh = rhs_s[kk][jx];
                float rc = rcs_s[kk][jx];
                float4 hv = *(const float4*)&hs[kk][byq * 4];
                aH0 = fmaf(hv.x, rh, aH0); aH1 = fmaf(hv.y, rh, aH1);
                aH2 = fmaf(hv.z, rh, aH2); aH3 = fmaf(hv.w, rh, aH3);
                aC0 = fmaf(hv.x, rc, aC0); aC1 = fmaf(hv.y, rc, aC1);
                aC2 = fmaf(hv.z, rc, aC2); aC3 = fmaf(hv.w, rc, aC3);
            }
        }
        __stcg((float4*)&g_part[0][kg][j0 + jx][byq * 4],
               make_float4(aH0, aH1, aH2, aH3));
        __stcg((float4*)&g_part[1][kg][j0 + jx][byq * 4],
               make_float4(aC0, aC1, aC2, aC3));
        gbar(tid, cta, base + (++bar));

        // ---- phase B: reduce + activations + highway combine ----
        {
            float sH = __ldcg(&g_part[0][0][ej][eb]) + __ldcg(&g_part[0][1][ej][eb])
                     + __ldcg(&g_part[0][2][ej][eb]) + __ldcg(&g_part[0][3][ej][eb]);
            float sC = __ldcg(&g_part[1][0][ej][eb]) + __ldcg(&g_part[1][1][ej][eb])
                     + __ldcg(&g_part[1][2][ej][eb]) + __ldcg(&g_part[1][3][ej][eb]);
            sH += RHb[l * H_SZ + ej];
            sC += RCb[l * H_SZ + ej];
            if (l == 0) {
                sH += __ldcg(&g_XHt[(size_t)t * (H_SZ * B_SZ) + e]);
                sC += __ldcg(&g_XCt[(size_t)t * (H_SZ * B_SZ) + e]);
            }
            float hold = __ldcg(&g_h[p][e]);
            float hl = tanhf(sH);
            float tl = 1.0f / (1.0f + __expf(-sC));
            float hn = fmaf(tl, hl - hold, hold);
            __stcg(&g_h[p ^ 1][e], hn);
            if (l == L_SZ - 1) {
                size_t o = (size_t)t * (B_SZ * 2 * H_SZ) + (size_t)eb * (2 * H_SZ)
                         + (size_t)pass * H_SZ + ej;
                out[o] = hn;
                if (t == T_LEN - 1) {
                    out[(size_t)T_LEN * (B_SZ * 2 * H_SZ) + (size_t)eb * (2 * H_SZ)
                        + (size_t)pass * H_SZ + ej] = hn;
                }
            }
        }
        gbar(tid, cta, base + (++bar));
        p ^= 1;
    }
}

extern "C" void kernel_launch(void* const* d_in, const int* in_sizes, int n_in,
                              void* d_out, int out_size)
{
    const float* x   = (const float*)d_in[0];
    const float* WHw = (const float*)d_in[1];
    const float* WHb = (const float*)d_in[2];
    const float* WCw = (const float*)d_in[3];
    const float* WCb = (const float*)d_in[4];
    const float* RHw = (const float*)d_in[5];
    const float* RHb = (const float*)d_in[6];
    const float* RCw = (const float*)d_in[7];
    const float* RCb = (const float*)d_in[8];
    float* out = (float*)d_out;

    bump_kernel<<<1, 1>>>();
    dim3 pg(256, 8);
    proj_kernel<<<pg, NTHR>>>(x, WHw, WHb, 0);
    proj_kernel<<<pg, NTHR>>>(x, WCw, WCb, 1);
    rhn_seq_kernel<<<NCTA, NTHR>>>(RHw, RHb, RCw, RCb, out);
}

// round 8
// speedup vs baseline: 2.2217x; 2.2156x over previous
#include <cuda_runtime.h>
#include <math.h>

#define T_LEN 512
#define B_SZ  64
#define D_SZ  1024
#define H_SZ  512
#define L_SZ  5

#define NGRP 8      // independent sync groups (8 batch columns each)
#define GCTA 16     // CTAs per group
#define BPG  8      // batch elements per group
#define NCTA (NGRP * GCTA)
#define NTHR 256

// ---------------- device-global scratch ----------------------------------------
__device__ float g_XHt[T_LEN * H_SZ * B_SZ];        // [t][j][b]
__device__ float g_XCt[T_LEN * H_SZ * B_SZ];        // [t][j][b]
__device__ float g_hh[2][NGRP][H_SZ][BPG];          // hidden dbl-buf [p][g][j][b]
__device__ float g_part[NGRP][2][4][H_SZ][BPG];     // [g][gate][kg][j][b]

struct __align__(256) Bar {
    unsigned cnt; unsigned pad1[63];
    unsigned rel; unsigned pad2[63];
};
__device__ Bar g_bar[NGRP];   // zero-init; monotonic forever (replay-safe)

// group-local ticket barrier (R2-proven pattern, 16 arrivals, self-derived phase)
__device__ __forceinline__ void gbar(int tid, int grp) {
    __syncthreads();
    if (tid == 0) {
        __threadfence();
        unsigned ticket = atomicAdd(&g_bar[grp].cnt, 1u);
        unsigned target = (ticket >> 4) + 1u;           // / GCTA
        if ((ticket & (GCTA - 1)) == (GCTA - 1)) {
            atomicExch(&g_bar[grp].rel, target);
        } else {
            while ((int)(*(volatile unsigned*)&g_bar[grp].rel - target) < 0) { }
        }
        __threadfence();
    }
    __syncthreads();
}

// ---------------- precompute: XHt/XCt[t][j][b] = x[t,b,:]@W[:,j] + bias[j] ------
__global__ void __launch_bounds__(NTHR) proj_kernel(
    const float* __restrict__ x,
    const float* __restrict__ Ww,
    const float* __restrict__ Wb,
    const int gate)
{
    __shared__ float As[32][128];
    __shared__ float Bs[32][64];
    float* __restrict__ dst = gate ? g_XCt : g_XHt;

    const int tid = threadIdx.x;
    const int bm  = blockIdx.x * 128;
    const int bn  = blockIdx.y * 64;
    const int tm  = tid & 15;
    const int tn  = tid >> 4;

    float acc[8][4];
#pragma unroll
    for (int i = 0; i < 8; i++)
#pragma unroll
        for (int j = 0; j < 4; j++) acc[i][j] = 0.0f;

    for (int k0 = 0; k0 < D_SZ; k0 += 32) {
#pragma unroll
        for (int r = 0; r < 4; r++) {
            int lin = tid + r * 256;
            int m = lin >> 3, kq = lin & 7;
            float4 v = *(const float4*)(x + (size_t)(bm + m) * D_SZ + k0 + kq * 4);
            As[kq * 4 + 0][m] = v.x;
            As[kq * 4 + 1][m] = v.y;
            As[kq * 4 + 2][m] = v.z;
            As[kq * 4 + 3][m] = v.w;
        }
#pragma unroll
        for (int r = 0; r < 2; r++) {
            int lin = tid + r * 256;
            int kk = lin >> 4, jq = lin & 15;
            *(float4*)&Bs[kk][jq * 4] =
                *(const float4*)(Ww + (size_t)(k0 + kk) * H_SZ + bn + jq * 4);
        }
        __syncthreads();
#pragma unroll
        for (int k = 0; k < 32; k++) {
            float4 a0 = *(const float4*)&As[k][tm * 4];
            float4 a1 = *(const float4*)&As[k][64 + tm * 4];
            float4 bv = *(const float4*)&Bs[k][tn * 4];
            float av[8] = {a0.x, a0.y, a0.z, a0.w, a1.x, a1.y, a1.z, a1.w};
            float bw[4] = {bv.x, bv.y, bv.z, bv.w};
#pragma unroll
            for (int i = 0; i < 8; i++)
#pragma unroll
                for (int j = 0; j < 4; j++)
                    acc[i][j] = fmaf(av[i], bw[j], acc[i][j]);
        }
        __syncthreads();
    }

#pragma unroll
    for (int i = 0; i < 8; i++) {
        int m = bm + ((i < 4) ? (tm * 4 + i) : (64 + tm * 4 + i - 4));
        int t = m >> 6, b = m & 63;
#pragma unroll
        for (int j = 0; j < 4; j++) {
            int jj = bn + tn * 4 + j;
            dst[(size_t)t * (H_SZ * B_SZ) + (size_t)jj * B_SZ + b] = acc[i][j] + Wb[jj];
        }
    }
}

// ---------------- persistent sequential kernel: 8 independent groups ------------
// Group = 16 CTAs (4 jg x 4 kg) x 8 batch columns. CTA tile: 128j x 128k x 8b x 2g.
// Thread = 2j x 4b x 1 gate (8 accs); per-k inner = LDS.128(h) + LDS.64(w) + 8 FMA.
// Weights streamed L2->smem in 4 chunks (reg-prefetch double buffer); h slice (4KB)
// staged once. Phase B: 1 element/thread, __expf activations. 2 group barriers/layer.
__global__ void __launch_bounds__(NTHR, 1) rhn_seq_kernel(
    const float* __restrict__ RHw, const float* __restrict__ RHb,
    const float* __restrict__ RCw, const float* __restrict__ RCb,
    float* __restrict__ out)
{
    __shared__ __align__(16) float h_s[128][8];        // 4 KB
    __shared__ __align__(16) float w_s[2][32][128];    // 32 KB

    const int tid = threadIdx.x;
    const int cta = blockIdx.x;
    const int grp = cta >> 4;
    const int cig = cta & 15;
    const int jg  = cig & 3;
    const int kg  = cig >> 2;
    const int j0  = jg * 128;
    const int k0  = kg * 128;
    const int b0  = grp * BPG;

    // phase-A compute mapping (warp-uniform gate/bq)
    const int jp   = tid & 63;        // j = j0 + jp*2 + {0,1}
    const int gate = (tid >> 6) & 1;
    const int bq   = tid >> 7;        // b = bq*4 + {0..3} (local)

    // phase-B mapping
    const int e   = cig * NTHR + tid; // 0..4095
    const int ej  = e >> 3;           // j
    const int ebb = e & 7;            // local b

    // zero h
    ((float*)g_hh[0][grp])[e] = 0.0f;

    // preload biases
    float bH[L_SZ], bC[L_SZ];
#pragma unroll
    for (int l = 0; l < L_SZ; l++) {
        bH[l] = RHb[l * H_SZ + ej];
        bC[l] = RCb[l * H_SZ + ej];
    }

    gbar(tid, grp);

    int p = 0;
    for (int pass = 0; pass < 2; pass++)
    for (int t = 0; t < T_LEN; t++)
    for (int l = 0; l < L_SZ; l++) {
        const float* __restrict__ Rh = RHw + (size_t)l * H_SZ * H_SZ;
        const float* __restrict__ Rc = RCw + (size_t)l * H_SZ * H_SZ;

        // stage h slice (128k x 8b = 256 float4) + prefetch w chunk 0
        float4 hv4 = ((const float4*)&g_hh[p][grp][k0][0])[tid];
        float4 wr[8];
#pragma unroll
        for (int r = 0; r < 8; r++) {
            int lin = tid + r * 256;
            int g   = lin >> 10;
            int rem = lin & 1023;
            int kk  = rem >> 5;
            int j4  = rem & 31;
            const float* src = g ? Rc : Rh;
            wr[r] = *(const float4*)(src + (size_t)(k0 + kk) * H_SZ + j0 + j4 * 4);
        }
        ((float4*)h_s)[tid] = hv4;
#pragma unroll
        for (int r = 0; r < 8; r++) {
            int lin = tid + r * 256;
            int g   = lin >> 10;
            int rem = lin & 1023;
            int kk  = rem >> 5;
            int j4  = rem & 31;
            *(float4*)&w_s[g][kk][j4 * 4] = wr[r];
        }
        __syncthreads();

        float4 accA = make_float4(0.f, 0.f, 0.f, 0.f);   // j_even, b0..3
        float4 accB = make_float4(0.f, 0.f, 0.f, 0.f);   // j_odd,  b0..3

#pragma unroll
        for (int c = 0; c < 4; c++) {
            if (c < 3) {
                const int kb = k0 + (c + 1) * 32;
#pragma unroll
                for (int r = 0; r < 8; r++) {
                    int lin = tid + r * 256;
                    int g   = lin >> 10;
                    int rem = lin & 1023;
                    int kk  = rem >> 5;
                    int j4  = rem & 31;
                    const float* src = g ? Rc : Rh;
                    wr[r] = *(const float4*)(src + (size_t)(kb + kk) * H_SZ + j0 + j4 * 4);
                }
            }
#pragma unroll
            for (int kk = 0; kk < 32; kk++) {
                float4 h4 = *(const float4*)&h_s[c * 32 + kk][bq * 4];
                float2 w2 = *(const float2*)&w_s[gate][kk][jp * 2];
                accA.x = fmaf(h4.x, w2.x, accA.x);
                accA.y = fmaf(h4.y, w2.x, accA.y);
                accA.z = fmaf(h4.z, w2.x, accA.z);
                accA.w = fmaf(h4.w, w2.x, accA.w);
                accB.x = fmaf(h4.x, w2.y, accB.x);
                accB.y = fmaf(h4.y, w2.y, accB.y);
                accB.z = fmaf(h4.z, w2.y, accB.z);
                accB.w = fmaf(h4.w, w2.y, accB.w);
            }
            if (c < 3) {
                __syncthreads();
#pragma unroll
                for (int r = 0; r < 8; r++) {
                    int lin = tid + r * 256;
                    int g   = lin >> 10;
                    int rem = lin & 1023;
                    int kk  = rem >> 5;
                    int j4  = rem & 31;
                    *(float4*)&w_s[g][kk][j4 * 4] = wr[r];
                }
                __syncthreads();
            }
        }

        {
            int j = j0 + jp * 2;
            *(float4*)&g_part[grp][gate][kg][j][bq * 4]     = accA;
            *(float4*)&g_part[grp][gate][kg][j + 1][bq * 4] = accB;
        }
        gbar(tid, grp);

        // ---- phase B ----
        {
            float sH = g_part[grp][0][0][ej][ebb] + g_part[grp][0][1][ej][ebb]
                     + g_part[grp][0][2][ej][ebb] + g_part[grp][0][3][ej][ebb];
            float sC = g_part[grp][1][0][ej][ebb] + g_part[grp][1][1][ej][ebb]
                     + g_part[grp][1][2][ej][ebb] + g_part[grp][1][3][ej][ebb];
            sH += bH[l];
            sC += bC[l];
            if (l == 0) {
                sH += g_XHt[(size_t)t * (H_SZ * B_SZ) + (size_t)ej * B_SZ + b0 + ebb];
                sC += g_XCt[(size_t)t * (H_SZ * B_SZ) + (size_t)ej * B_SZ + b0 + ebb];
            }
            float hold = g_hh[p][grp][ej][ebb];
            float hl = 1.0f - 2.0f / (1.0f + __expf(2.0f * sH));   // tanh
            float tl = 1.0f / (1.0f + __expf(-sC));                // sigmoid
            float hn = fmaf(tl, hl - hold, hold);
            g_hh[p ^ 1][grp][ej][ebb] = hn;
            if (l == L_SZ - 1) {
                size_t o = (size_t)t * (B_SZ * 2 * H_SZ)
                         + (size_t)(b0 + ebb) * (2 * H_SZ)
                         + (size_t)pass * H_SZ + ej;
                out[o] = hn;
                if (t == T_LEN - 1) {
                    out[(size_t)T_LEN * (B_SZ * 2 * H_SZ)
                        + (size_t)(b0 + ebb) * (2 * H_SZ)
                        + (size_t)pass * H_SZ + ej] = hn;
                }
            }
        }
        gbar(tid, grp);
        p ^= 1;
    }
}

extern "C" void kernel_launch(void* const* d_in, const int* in_sizes, int n_in,
                              void* d_out, int out_size)
{
    const float* x   = (const float*)d_in[0];
    const float* WHw = (const float*)d_in[1];
    const float* WHb = (const float*)d_in[2];
    const float* WCw = (const float*)d_in[3];
    const float* WCb = (const float*)d_in[4];
    const float* RHw = (const float*)d_in[5];
    const float* RHb = (const float*)d_in[6];
    const float* RCw = (const float*)d_in[7];
    const float* RCb = (const float*)d_in[8];
    float* out = (float*)d_out;

    dim3 pg(256, 8);
    proj_kernel<<<pg, NTHR>>>(x, WHw, WHb, 0);
    proj_kernel<<<pg, NTHR>>>(x, WCw, WCb, 1);
    rhn_seq_kernel<<<NCTA, NTHR>>>(RHw, RHb, RCw, RCb, out);
}